// round 6
// baseline (speedup 1.0000x reference)
#include <cuda_runtime.h>
#include <cstdint>

// Problem constants
#define BS   32
#define CLS  80
#define HH   128
#define WW   128
#define HW   16384
#define K    100
#define CAND_CAP  3072   // ~35 sigma above expected ~1850 peaks
#define FINAL_CAP 256

// Output layout (fp32, concatenated in reference return order)
#define OFF_SC   0                      // (32,80,100) per-class topk scores
#define OFF_IND  (BS*CLS*K)             // 256000
#define OFF_CLSO (OFF_IND + BS*K)       // 259200
#define OFF_YS   (OFF_CLSO + BS*K)      // 262400
#define OFF_XS   (OFF_YS + BS*K)        // 265600

// Scratch: per-class top-100 flat spatial indices
__device__ int g_idx1[BS * CLS * K];

__device__ __forceinline__ unsigned long long make_key(unsigned sb, unsigned idx) {
    // max-order == (score desc, idx asc); scores >= 0 so bit pattern is monotone
    return ((unsigned long long)sb << 32) | (unsigned)(~idx);
}

// Warp-aggregated histogram add: lanes with equal digit merge into one atomic.
// digit must be in [0,256]; 256 = "skip" sentinel. ALL 32 lanes must call.
__device__ __forceinline__ void hist_add(int* s_hist, int digit, int lane) {
    unsigned mk = __match_any_sync(0xFFFFFFFFu, digit);
    if (digit < 256 && (mk & ((1u << lane) - 1u)) == 0)   // leader lane
        atomicAdd(&s_hist[digit], __popc(mk));
}

// Inclusive suffix-scan over 256 histogram bins.
// After call: s_scan[p] = sum of s_hist[255-p .. 255]  (suffix(d) = s_scan[255-d]).
__device__ __forceinline__ void suffix_scan_store(const int* s_hist, int* s_scan,
                                                  int* s_red, int tid, int lane, int warp) {
    int incl = s_hist[255 - tid];
    #pragma unroll
    for (int o = 1; o < 32; o <<= 1) {
        int x = __shfl_up_sync(0xFFFFFFFFu, incl, o);
        if (lane >= o) incl += x;
    }
    if (lane == 31) s_red[warp] = incl;
    __syncthreads();
    int off = 0;
    #pragma unroll
    for (int w = 0; w < 8; ++w) off += (w < warp) ? s_red[w] : 0;
    s_scan[tid] = incl + off;
    __syncthreads();
}

// Load 10 floats (cols c0-1 .. c0+8) of row r, NEG-filled out of bounds.
__device__ __forceinline__ void load10(const float* __restrict__ t, int r, int c0,
                                       bool hasL, bool hasR, float v[10]) {
    const float NEG = -3.0e38f;
    if ((unsigned)r >= (unsigned)HH) {
        #pragma unroll
        for (int j = 0; j < 10; ++j) v[j] = NEG;
        return;
    }
    const float* row = t + r * WW + c0;
    float4 a = *(const float4*)row;
    float4 b = *(const float4*)(row + 4);
    v[0] = hasL ? __ldg(row - 1) : NEG;
    v[1] = a.x; v[2] = a.y; v[3] = a.z; v[4] = a.w;
    v[5] = b.x; v[6] = b.y; v[7] = b.z; v[8] = b.w;
    v[9] = hasR ? __ldg(row + 8) : NEG;
}

// ---------------------------------------------------------------------------
// Stage 1: one CTA per (b,c). 8x8 strip rolling NMS + radix-select top-100.
// Exact JAX order: score desc, flat idx asc.
// ---------------------------------------------------------------------------
__global__ void __launch_bounds__(256, 4)
stage1_kernel(const float* __restrict__ hm, float* __restrict__ out)
{
    __shared__ unsigned long long s_cand[CAND_CAP];
    __shared__ unsigned long long s_final[FINAL_CAP];
    __shared__ int s_hist[256];
    __shared__ int s_scan[256];
    __shared__ int s_red[8];
    __shared__ int s_sel;
    __shared__ int s_ncand, s_nfinal;

    const int bc   = blockIdx.x;           // 0..2559
    const int tid  = threadIdx.x;
    const int lane = tid & 31;
    const int warp = tid >> 5;
    const float* __restrict__ t = hm + (size_t)bc * HW;

    if (tid == 0) { s_ncand = 0; s_nfinal = 0; }
    __syncthreads();

    // --- NMS: thread owns 8-col strip x 8 rows -----------------------------
    const int c0 = (tid & 15) << 3;        // 0,8,...,120
    const int r0 = (tid >> 4) << 3;        // 16 bands of 8 rows
    const bool hasL = (c0 > 0);
    const bool hasR = (c0 < WW - 8);

    float Bv[10], pm[10], Cv[10];
    load10(t, r0 - 1, c0, hasL, hasR, pm);     // row above (as A)
    load10(t, r0,     c0, hasL, hasR, Bv);     // center row
    #pragma unroll
    for (int j = 0; j < 10; ++j) pm[j] = fmaxf(pm[j], Bv[j]);   // pm = max(A,B)

    #pragma unroll
    for (int rr = 0; rr < 8; ++rr) {
        const int r = r0 + rr;
        load10(t, r + 1, c0, hasL, hasR, Cv);

        float vm[10];
        #pragma unroll
        for (int j = 0; j < 10; ++j) vm[j] = fmaxf(pm[j], Cv[j]);  // 3-row col max
        float tj[9];
        #pragma unroll
        for (int j = 0; j < 9; ++j) tj[j] = fmaxf(vm[j], vm[j + 1]);

        unsigned mask = 0;
        #pragma unroll
        for (int j = 0; j < 8; ++j)
            mask |= (fmaxf(tj[j], vm[j + 2]) == Bv[j + 1]) ? (1u << j) : 0u;

        int n = __popc(mask);
        int incl = n;
        #pragma unroll
        for (int o = 1; o < 32; o <<= 1) {
            int x = __shfl_up_sync(0xFFFFFFFFu, incl, o);
            if (lane >= o) incl += x;
        }
        int wtot = __shfl_sync(0xFFFFFFFFu, incl, 31);
        if (wtot) {
            int base = 0;
            if (lane == 31) base = atomicAdd(&s_ncand, wtot);
            base = __shfl_sync(0xFFFFFFFFu, base, 31);
            int pos = base + incl - n;
            const int cb = r * WW + c0;
            if (mask & 1u)   { if (pos < CAND_CAP) s_cand[pos] = make_key(__float_as_uint(Bv[1]), cb + 0); pos++; }
            if (mask & 2u)   { if (pos < CAND_CAP) s_cand[pos] = make_key(__float_as_uint(Bv[2]), cb + 1); pos++; }
            if (mask & 4u)   { if (pos < CAND_CAP) s_cand[pos] = make_key(__float_as_uint(Bv[3]), cb + 2); pos++; }
            if (mask & 8u)   { if (pos < CAND_CAP) s_cand[pos] = make_key(__float_as_uint(Bv[4]), cb + 3); pos++; }
            if (mask & 16u)  { if (pos < CAND_CAP) s_cand[pos] = make_key(__float_as_uint(Bv[5]), cb + 4); pos++; }
            if (mask & 32u)  { if (pos < CAND_CAP) s_cand[pos] = make_key(__float_as_uint(Bv[6]), cb + 5); pos++; }
            if (mask & 64u)  { if (pos < CAND_CAP) s_cand[pos] = make_key(__float_as_uint(Bv[7]), cb + 6); pos++; }
            if (mask & 128u) { if (pos < CAND_CAP) s_cand[pos] = make_key(__float_as_uint(Bv[8]), cb + 7); pos++; }
        }

        #pragma unroll
        for (int j = 0; j < 10; ++j) { pm[j] = fmaxf(Bv[j], Cv[j]); Bv[j] = Cv[j]; }
    }
    __syncthreads();
    int ncand = min(s_ncand, CAND_CAP);

    // --- Pathological fallback: <100 peaks -> append zero-score non-peaks ---
    if (ncand < K) {
        int idx = tid;                     // first 256 cells contain the 100
        int r = idx >> 7, c = idx & (WW - 1);
        float v = t[idx];
        float m = v;
        for (int dr = -1; dr <= 1; ++dr)
            for (int dc = -1; dc <= 1; ++dc) {
                int rr2 = r + dr, cc = c + dc;
                if (rr2 >= 0 && rr2 < HH && cc >= 0 && cc < WW)
                    m = fmaxf(m, t[rr2 * WW + cc]);
            }
        if (m != v) {   // suppressed: value 0 after keep-mask
            int p = atomicAdd(&s_ncand, 1);
            if (p < CAND_CAP) s_cand[p] = make_key(0u, idx);
        }
        __syncthreads();
        ncand = min(s_ncand, CAND_CAP);
    }
    const int npad = (ncand + 255) & ~255;   // padded bound for full-warp match

    // --- Radix-select: find floor Tf with count(>=Tf) in [K, FINAL_CAP] -----
    int need = K;
    int total_above = 0;
    unsigned long long prefix = 0;
    unsigned long long Tf = 0;
    for (int shift = 56;; shift -= 8) {
        s_hist[tid] = 0;
        __syncthreads();
        for (int i = tid; i < npad; i += 256) {
            int digit = 256;
            if (i < ncand) {
                unsigned long long sh = s_cand[i] >> shift;
                if ((sh >> 8) == prefix) digit = (int)(sh & 255u);
            }
            hist_add(s_hist, digit, lane);
        }
        __syncthreads();
        suffix_scan_store(s_hist, s_scan, s_red, tid, lane, warp);
        {
            int d = tid;
            int suf  = s_scan[255 - d];
            int suf1 = (d == 255) ? 0 : s_scan[254 - d];
            if (suf >= need && suf1 < need) s_sel = d;
        }
        __syncthreads();
        int dsel  = s_sel;
        int A     = (dsel == 255) ? 0 : s_scan[254 - dsel];
        int inbin = s_scan[255 - dsel] - A;
        prefix = (prefix << 8) | (unsigned)dsel;
        total_above += A;
        need -= A;
        if (total_above + inbin <= FINAL_CAP || shift == 0) {
            Tf = prefix << shift;
            break;
        }
        __syncthreads();   // protect s_sel/s_scan before next round overwrites
    }
    __syncthreads();

    // --- Collect survivors (<=256) and rank-emit ---------------------------
    for (int i = tid; i < ncand; i += 256) {
        unsigned long long kk = s_cand[i];
        if (kk >= Tf) {
            int p = atomicAdd(&s_nfinal, 1);
            if (p < FINAL_CAP) s_final[p] = kk;
        }
    }
    __syncthreads();
    int nf = min(s_nfinal, FINAL_CAP);

    if (tid < nf) {
        unsigned long long my = s_final[tid];
        int rank = 0;
        #pragma unroll 4
        for (int i = 0; i < nf; ++i) rank += (s_final[i] > my) ? 1 : 0;
        if (rank < K) {
            out[OFF_SC + bc * K + rank] = __uint_as_float((unsigned)(my >> 32));
            g_idx1[bc * K + rank] = (int)(~(unsigned)my);
        }
    }
}

// ---------------------------------------------------------------------------
// Stage 2: one CTA per batch. Global top-100 over C*K=8000 per-class scores
// via the same radix-select. 48-bit keys: (score<<16) | (0xFFFF & ~i).
// ---------------------------------------------------------------------------
__device__ __forceinline__ unsigned long long key2(unsigned sb, int i) {
    return ((unsigned long long)sb << 16) | (unsigned)(0xFFFFu & ~(unsigned)i);
}

__global__ void __launch_bounds__(256)
stage2_kernel(const float* __restrict__ out_scores, float* __restrict__ out)
{
    __shared__ unsigned s_sc[CLS * K];               // 8000 * 4B
    __shared__ unsigned long long s_final[FINAL_CAP];
    __shared__ int s_hist[256];
    __shared__ int s_scan[256];
    __shared__ int s_red[8];
    __shared__ int s_sel;
    __shared__ int s_nfinal;

    const int b    = blockIdx.x;
    const int tid  = threadIdx.x;
    const int lane = tid & 31;
    const int warp = tid >> 5;
    const int NC   = CLS * K;                        // 8000
    const int NCP  = (NC + 255) & ~255;              // 8192 padded
    const float* __restrict__ sc = out_scores + OFF_SC + (size_t)b * NC;

    if (tid == 0) s_nfinal = 0;
    for (int i = tid; i < NC; i += 256) s_sc[i] = __float_as_uint(sc[i]);
    __syncthreads();

    int need = K;
    int total_above = 0;
    unsigned long long prefix = 0;
    unsigned long long Tf = 0;
    for (int shift = 40;; shift -= 8) {
        s_hist[tid] = 0;
        __syncthreads();
        for (int i = tid; i < NCP; i += 256) {
            int digit = 256;
            if (i < NC) {
                unsigned long long sh = key2(s_sc[i], i) >> shift;
                if ((sh >> 8) == prefix) digit = (int)(sh & 255u);
            }
            hist_add(s_hist, digit, lane);
        }
        __syncthreads();
        suffix_scan_store(s_hist, s_scan, s_red, tid, lane, warp);
        {
            int d = tid;
            int suf  = s_scan[255 - d];
            int suf1 = (d == 255) ? 0 : s_scan[254 - d];
            if (suf >= need && suf1 < need) s_sel = d;
        }
        __syncthreads();
        int dsel  = s_sel;
        int A     = (dsel == 255) ? 0 : s_scan[254 - dsel];
        int inbin = s_scan[255 - dsel] - A;
        prefix = (prefix << 8) | (unsigned)dsel;
        total_above += A;
        need -= A;
        if (total_above + inbin <= FINAL_CAP || shift == 0) {
            Tf = prefix << shift;
            break;
        }
        __syncthreads();
    }
    __syncthreads();

    for (int i = tid; i < NC; i += 256) {
        unsigned long long kk = key2(s_sc[i], i);
        if (kk >= Tf) {
            int p = atomicAdd(&s_nfinal, 1);
            if (p < FINAL_CAP) s_final[p] = kk;
        }
    }
    __syncthreads();
    int nf = min(s_nfinal, FINAL_CAP);

    if (tid < nf) {
        unsigned long long my = s_final[tid];
        int rank = 0;
        #pragma unroll 4
        for (int i = 0; i < nf; ++i) rank += (s_final[i] > my) ? 1 : 0;
        if (rank < K) {
            int ci     = (int)((~(unsigned)my) & 0xFFFFu);   // combined idx [0,8000)
            int classe = ci / K;
            int flat   = g_idx1[b * NC + ci];
            out[OFF_IND  + b * K + rank] = (float)flat;
            out[OFF_CLSO + b * K + rank] = (float)classe;
            out[OFF_YS   + b * K + rank] = (float)(flat >> 7);   // y = flat / 128
            out[OFF_XS   + b * K + rank] = (float)(flat & 127);  // x = flat % 128
        }
    }
}

// ---------------------------------------------------------------------------
extern "C" void kernel_launch(void* const* d_in, const int* in_sizes, int n_in,
                              void* d_out, int out_size)
{
    const float* hm = (const float*)d_in[0];
    float* out = (float*)d_out;
    stage1_kernel<<<BS * CLS, 256>>>(hm, out);
    stage2_kernel<<<BS, 256>>>(out, out);
}

// round 7
// speedup vs baseline: 1.1536x; 1.1536x over previous
#include <cuda_runtime.h>
#include <cstdint>

// Problem constants
#define BS   32
#define CLS  80
#define HH   128
#define WW   128
#define HW   16384
#define K    100
#define CAND_CAP  4096   // u64 slots; doubles as 8192-u32 score cache for stage2
#define FINAL_CAP 256

// Output layout (fp32, concatenated in reference return order)
#define OFF_SC   0                      // (32,80,100) per-class topk scores
#define OFF_IND  (BS*CLS*K)             // 256000
#define OFF_CLSO (OFF_IND + BS*K)       // 259200
#define OFF_YS   (OFF_CLSO + BS*K)      // 262400
#define OFF_XS   (OFF_YS + BS*K)        // 265600

// Scratch: per-class top-100 flat spatial indices
__device__ int g_idx1[BS * CLS * K];
// Per-batch completion counters (zero-init; reset by consumer -> graph-safe)
__device__ int g_done[BS];

__device__ __forceinline__ unsigned long long make_key(unsigned sb, unsigned idx) {
    // max-order == (score desc, idx asc); scores >= 0 so bit pattern is monotone
    return ((unsigned long long)sb << 32) | (unsigned)(~idx);
}

__device__ __forceinline__ unsigned long long key2(unsigned sb, int i) {
    return ((unsigned long long)sb << 16) | (unsigned)(0xFFFFu & ~(unsigned)i);
}

// Inclusive suffix-scan over 256 histogram bins.
// After call: s_scan[p] = sum of s_hist[255-p .. 255]  (suffix(d) = s_scan[255-d]).
__device__ __forceinline__ void suffix_scan_store(const int* s_hist, int* s_scan,
                                                  int* s_red, int tid, int lane, int warp) {
    int incl = s_hist[255 - tid];
    #pragma unroll
    for (int o = 1; o < 32; o <<= 1) {
        int x = __shfl_up_sync(0xFFFFFFFFu, incl, o);
        if (lane >= o) incl += x;
    }
    if (lane == 31) s_red[warp] = incl;
    __syncthreads();
    int off = 0;
    #pragma unroll
    for (int w = 0; w < 8; ++w) off += (w < warp) ? s_red[w] : 0;
    s_scan[tid] = incl + off;
    __syncthreads();
}

// Load 10 floats (cols c0-1 .. c0+8) of row r, NEG-filled out of bounds.
__device__ __forceinline__ void load10(const float* __restrict__ t, int r, int c0,
                                       bool hasL, bool hasR, float v[10]) {
    const float NEG = -3.0e38f;
    if ((unsigned)r >= (unsigned)HH) {
        #pragma unroll
        for (int j = 0; j < 10; ++j) v[j] = NEG;
        return;
    }
    const float* row = t + r * WW + c0;
    float4 a = *(const float4*)row;
    float4 b = *(const float4*)(row + 4);
    v[0] = hasL ? __ldg(row - 1) : NEG;
    v[1] = a.x; v[2] = a.y; v[3] = a.z; v[4] = a.w;
    v[5] = b.x; v[6] = b.y; v[7] = b.z; v[8] = b.w;
    v[9] = hasR ? __ldg(row + 8) : NEG;
}

// ---------------------------------------------------------------------------
// Fused kernel: one CTA per (b,c). NMS + per-class radix top-100; the last
// CTA of each batch additionally runs the global top-100 (stage2) inline.
// ---------------------------------------------------------------------------
__global__ void __launch_bounds__(256, 4)
decode_kernel(const float* __restrict__ hm, float* __restrict__ out)
{
    __shared__ unsigned long long s_cand[CAND_CAP];   // 32 KB; aliased by stage2
    __shared__ unsigned long long s_final[FINAL_CAP];
    __shared__ int s_hist[256];
    __shared__ int s_scan[256];
    __shared__ int s_red[8];
    __shared__ int s_sel;
    __shared__ int s_ncand, s_nfinal, s_last;

    const int bc   = blockIdx.x;           // 0..2559
    const int b    = bc / CLS;
    const int tid  = threadIdx.x;
    const int lane = tid & 31;
    const int warp = tid >> 5;
    const float* __restrict__ t = hm + (size_t)bc * HW;

    if (tid == 0) { s_ncand = 0; s_nfinal = 0; }
    __syncthreads();

    // --- NMS: thread owns 8-col strip x 8 rows -----------------------------
    const int c0 = (tid & 15) << 3;        // 0,8,...,120
    const int r0 = (tid >> 4) << 3;        // 16 bands of 8 rows
    const bool hasL = (c0 > 0);
    const bool hasR = (c0 < WW - 8);

    float Bv[10], pm[10], Cv[10];
    load10(t, r0 - 1, c0, hasL, hasR, pm);     // row above (as A)
    load10(t, r0,     c0, hasL, hasR, Bv);     // center row
    #pragma unroll
    for (int j = 0; j < 10; ++j) pm[j] = fmaxf(pm[j], Bv[j]);   // pm = max(A,B)

    #pragma unroll
    for (int rr = 0; rr < 8; ++rr) {
        const int r = r0 + rr;
        load10(t, r + 1, c0, hasL, hasR, Cv);

        float vm[10];
        #pragma unroll
        for (int j = 0; j < 10; ++j) vm[j] = fmaxf(pm[j], Cv[j]);  // 3-row col max
        float tj[9];
        #pragma unroll
        for (int j = 0; j < 9; ++j) tj[j] = fmaxf(vm[j], vm[j + 1]);

        unsigned mask = 0;
        #pragma unroll
        for (int j = 0; j < 8; ++j)
            mask |= (fmaxf(tj[j], vm[j + 2]) == Bv[j + 1]) ? (1u << j) : 0u;

        int n = __popc(mask);
        int incl = n;
        #pragma unroll
        for (int o = 1; o < 32; o <<= 1) {
            int x = __shfl_up_sync(0xFFFFFFFFu, incl, o);
            if (lane >= o) incl += x;
        }
        int wtot = __shfl_sync(0xFFFFFFFFu, incl, 31);
        if (wtot) {
            int base = 0;
            if (lane == 31) base = atomicAdd(&s_ncand, wtot);
            base = __shfl_sync(0xFFFFFFFFu, base, 31);
            int pos = base + incl - n;
            const int cb = r * WW + c0;
            if (mask & 1u)   { if (pos < CAND_CAP) s_cand[pos] = make_key(__float_as_uint(Bv[1]), cb + 0); pos++; }
            if (mask & 2u)   { if (pos < CAND_CAP) s_cand[pos] = make_key(__float_as_uint(Bv[2]), cb + 1); pos++; }
            if (mask & 4u)   { if (pos < CAND_CAP) s_cand[pos] = make_key(__float_as_uint(Bv[3]), cb + 2); pos++; }
            if (mask & 8u)   { if (pos < CAND_CAP) s_cand[pos] = make_key(__float_as_uint(Bv[4]), cb + 3); pos++; }
            if (mask & 16u)  { if (pos < CAND_CAP) s_cand[pos] = make_key(__float_as_uint(Bv[5]), cb + 4); pos++; }
            if (mask & 32u)  { if (pos < CAND_CAP) s_cand[pos] = make_key(__float_as_uint(Bv[6]), cb + 5); pos++; }
            if (mask & 64u)  { if (pos < CAND_CAP) s_cand[pos] = make_key(__float_as_uint(Bv[7]), cb + 6); pos++; }
            if (mask & 128u) { if (pos < CAND_CAP) s_cand[pos] = make_key(__float_as_uint(Bv[8]), cb + 7); pos++; }
        }

        #pragma unroll
        for (int j = 0; j < 10; ++j) { pm[j] = fmaxf(Bv[j], Cv[j]); Bv[j] = Cv[j]; }
    }
    __syncthreads();
    int ncand = min(s_ncand, CAND_CAP);

    // --- Pathological fallback: <100 peaks -> append zero-score non-peaks ---
    if (ncand < K) {
        int idx = tid;                     // first 256 cells contain the 100
        int r = idx >> 7, c = idx & (WW - 1);
        float v = t[idx];
        float m = v;
        for (int dr = -1; dr <= 1; ++dr)
            for (int dc = -1; dc <= 1; ++dc) {
                int rr2 = r + dr, cc = c + dc;
                if (rr2 >= 0 && rr2 < HH && cc >= 0 && cc < WW)
                    m = fmaxf(m, t[rr2 * WW + cc]);
            }
        if (m != v) {   // suppressed: value 0 after keep-mask
            int p = atomicAdd(&s_ncand, 1);
            if (p < CAND_CAP) s_cand[p] = make_key(0u, idx);
        }
        __syncthreads();
        ncand = min(s_ncand, CAND_CAP);
    }

    // --- Radix-select: floor Tf with count(>=Tf) in [K, FINAL_CAP] ----------
    {
        int need = K;
        int total_above = 0;
        unsigned long long prefix = 0;
        unsigned long long Tf = 0;
        for (int shift = 56;; shift -= 8) {
            s_hist[tid] = 0;
            __syncthreads();
            for (int i = tid; i < ncand; i += 256) {
                unsigned long long sh = s_cand[i] >> shift;
                if ((sh >> 8) == prefix) atomicAdd(&s_hist[(int)(sh & 255u)], 1);
            }
            __syncthreads();
            suffix_scan_store(s_hist, s_scan, s_red, tid, lane, warp);
            {
                int d = tid;
                int suf  = s_scan[255 - d];
                int suf1 = (d == 255) ? 0 : s_scan[254 - d];
                if (suf >= need && suf1 < need) s_sel = d;
            }
            __syncthreads();
            int dsel  = s_sel;
            int A     = (dsel == 255) ? 0 : s_scan[254 - dsel];
            int inbin = s_scan[255 - dsel] - A;
            prefix = (prefix << 8) | (unsigned)dsel;
            total_above += A;
            need -= A;
            if (total_above + inbin <= FINAL_CAP || shift == 0) {
                Tf = prefix << shift;
                break;
            }
            __syncthreads();
        }
        __syncthreads();

        // --- Collect survivors (<=256) and rank-emit -------------------------
        for (int i = tid; i < ncand; i += 256) {
            unsigned long long kk = s_cand[i];
            if (kk >= Tf) {
                int p = atomicAdd(&s_nfinal, 1);
                if (p < FINAL_CAP) s_final[p] = kk;
            }
        }
        __syncthreads();
        int nf = min(s_nfinal, FINAL_CAP);

        if (tid < nf) {
            unsigned long long my = s_final[tid];
            int rank = 0;
            #pragma unroll 4
            for (int i = 0; i < nf; ++i) rank += (s_final[i] > my) ? 1 : 0;
            if (rank < K) {
                out[OFF_SC + bc * K + rank] = __uint_as_float((unsigned)(my >> 32));
                g_idx1[bc * K + rank] = (int)(~(unsigned)my);
            }
        }
    }

    // --- Batch completion: last CTA of batch b runs stage2 inline -----------
    __threadfence();
    __syncthreads();
    if (tid == 0) {
        int v = atomicAdd(&g_done[b], 1);
        s_last = (v == CLS - 1) ? 1 : 0;
        if (v == CLS - 1) atomicExch(&g_done[b], 0);   // reset for graph replay
    }
    __syncthreads();
    if (!s_last) return;
    __threadfence();

    // ======================= Inline stage 2 for batch b ======================
    unsigned* s_sc = (unsigned*)s_cand;                // 8000 u32 in 32 KB buffer
    const int NC = CLS * K;                            // 8000
    const float* __restrict__ sc = out + OFF_SC + (size_t)b * NC;

    if (tid == 0) s_nfinal = 0;
    for (int i = tid; i < NC; i += 256) s_sc[i] = __float_as_uint(sc[i]);
    __syncthreads();

    int need = K;
    int total_above = 0;
    unsigned long long prefix = 0;
    unsigned long long Tf = 0;
    for (int shift = 40;; shift -= 8) {
        s_hist[tid] = 0;
        __syncthreads();
        for (int i = tid; i < NC; i += 256) {
            unsigned long long sh = key2(s_sc[i], i) >> shift;
            if ((sh >> 8) == prefix) atomicAdd(&s_hist[(int)(sh & 255u)], 1);
        }
        __syncthreads();
        suffix_scan_store(s_hist, s_scan, s_red, tid, lane, warp);
        {
            int d = tid;
            int suf  = s_scan[255 - d];
            int suf1 = (d == 255) ? 0 : s_scan[254 - d];
            if (suf >= need && suf1 < need) s_sel = d;
        }
        __syncthreads();
        int dsel  = s_sel;
        int A     = (dsel == 255) ? 0 : s_scan[254 - dsel];
        int inbin = s_scan[255 - dsel] - A;
        prefix = (prefix << 8) | (unsigned)dsel;
        total_above += A;
        need -= A;
        if (total_above + inbin <= FINAL_CAP || shift == 0) {
            Tf = prefix << shift;
            break;
        }
        __syncthreads();
    }
    __syncthreads();

    for (int i = tid; i < NC; i += 256) {
        unsigned long long kk = key2(s_sc[i], i);
        if (kk >= Tf) {
            int p = atomicAdd(&s_nfinal, 1);
            if (p < FINAL_CAP) s_final[p] = kk;
        }
    }
    __syncthreads();
    int nf = min(s_nfinal, FINAL_CAP);

    if (tid < nf) {
        unsigned long long my = s_final[tid];
        int rank = 0;
        #pragma unroll 4
        for (int i = 0; i < nf; ++i) rank += (s_final[i] > my) ? 1 : 0;
        if (rank < K) {
            int ci     = (int)((~(unsigned)my) & 0xFFFFu);   // combined idx [0,8000)
            int classe = ci / K;
            int flat   = g_idx1[b * NC + ci];
            out[OFF_IND  + b * K + rank] = (float)flat;
            out[OFF_CLSO + b * K + rank] = (float)classe;
            out[OFF_YS   + b * K + rank] = (float)(flat >> 7);   // y = flat / 128
            out[OFF_XS   + b * K + rank] = (float)(flat & 127);  // x = flat % 128
        }
    }
}

// ---------------------------------------------------------------------------
extern "C" void kernel_launch(void* const* d_in, const int* in_sizes, int n_in,
                              void* d_out, int out_size)
{
    const float* hm = (const float*)d_in[0];
    float* out = (float*)d_out;
    decode_kernel<<<BS * CLS, 256>>>(hm, out);
}